// round 12
// baseline (speedup 1.0000x reference)
#include <cuda_runtime.h>
#include <cuda.h>

// BilinearResNet fused, GB300 sm_103a — round 12
// Warp-private TMA rings (3-deep, 32 rows/warp) -> ZERO mainloop barriers.
// R=4 x C=4 f32x2 tile, W via __ldg, TROWS=128/NTH=128/grid=512, 4 CTAs/SM.

#define IN_DIM 784
#define DM     16
#define HID    6
#define NB     4
#define NC     10
#define KC     28            // floats per k-chunk (112B rows: conflict-free)
#define NCHUNK 28            // 784 / 28
#define NKQ    7             // float4 groups per chunk
#define TROWS  128           // rows per CTA tile
#define NTH    128
#define NWARP  4
#define NBUF   3
#define WROWS  32            // rows per warp

// per-warp buffer: 32 rows x 28 floats = 896 floats (3584 B)
#define WXB    (WROWS*KC)
// smem float offsets
#define XS     0                              // 4*3*896 = 10752 floats
#define HXS    (NWARP*NBUF*WXB)               // 10752, hx tile 128*17 = 2176
#define MBAR_F (HXS + TROWS*17)               // 12928 (byte 51712, 8B aligned)
#define SMEM_FLOATS (MBAR_F + 2*NWARP*NBUF)   // +24 = 12952 floats (51808 B)

// reordered weights in global (written by pre-kernel)
__device__ __align__(16) float g_Wq[DM * IN_DIM];     // [kq][jj][cg][k4]
__device__ __align__(16) float g_Dt[NB * DM * HID];   // [i][a][j]

__global__ void reorder_kernel(const float* __restrict__ We,
                               const float* __restrict__ Dw) {
    int idx = blockIdx.x * 256 + threadIdx.x;
    if (idx < DM * IN_DIM) {
        int j = idx / IN_DIM, k = idx - j * IN_DIM;
        // col j = jj*4 + cg ; offset = kq*64 + jj*16 + cg*4 + k4
        g_Wq[(k >> 2) * (DM * 4) + (j >> 2) * 16 + (j & 3) * 4 + (k & 3)] = We[idx];
    }
    if (idx < NB * DM * HID) {
        int i = idx / (DM * HID), r = idx % (DM * HID);
        int j = r / HID, a = r % HID;
        g_Dt[i * (DM * HID) + a * DM + j] = Dw[idx];
    }
}

__device__ __forceinline__ void fma2(unsigned long long& acc,
                                     unsigned long long a, unsigned long long b) {
    asm("fma.rn.f32x2 %0, %1, %2, %0;" : "+l"(acc) : "l"(a), "l"(b));
}
__device__ __forceinline__ float red2(unsigned long long a) {
    return __uint_as_float((unsigned)a) + __uint_as_float((unsigned)(a >> 32));
}

#define MB_INIT(addr, cnt) \
    asm volatile("mbarrier.init.shared.b64 [%0], %1;" :: "r"(addr), "r"(cnt) : "memory")
#define MB_EXPECT_TX(addr, bytes) \
    asm volatile("mbarrier.arrive.expect_tx.shared.b64 _, [%0], %1;" :: "r"(addr), "r"(bytes) : "memory")
#define MB_WAIT(addr, parity) do {                                                  \
    asm volatile("{\n\t.reg .pred P;\n"                                             \
        "WLP%=:\n\tmbarrier.try_wait.parity.acquire.cta.shared::cta.b64 P, [%0], %1, 0x989680;\n" \
        "\t@P bra WDN%=;\n\tbra WLP%=;\nWDN%=:\n\t}"                                \
        :: "r"(addr), "r"(parity) : "memory"); } while (0)
#define TMA_2D(dst, tmapp, cx, cy, mb)                                              \
    asm volatile("cp.async.bulk.tensor.2d.shared::cta.global.tile.mbarrier::complete_tx::bytes " \
        "[%0], [%1, {%2, %3}], [%4];"                                               \
        :: "r"(dst), "l"(tmapp), "r"(cx), "r"(cy), "r"(mb) : "memory")

__global__ __launch_bounds__(NTH, 4)
void bilinear_resnet_kernel(const __grid_constant__ CUtensorMap tmap,
                            const float* __restrict__ Lw,
                            const float* __restrict__ Rw,
                            const float* __restrict__ Wh,
                            float* __restrict__ out,
                            int batch)
{
    extern __shared__ float sm[];
    const int tid = threadIdx.x;
    const unsigned smbase = (unsigned)__cvta_generic_to_shared(sm);
    const int row0 = blockIdx.x * TROWS;

    const int warp = tid >> 5, lane = tid & 31;
    const int rs = lane >> 2;          // 0..7 rowset within warp's 32 rows
    const int cg = lane & 3;           // cols cg, cg+4, cg+8, cg+12
    const int wrow0 = row0 + warp * WROWS;     // this warp's global row base

    // this warp's buffers + barriers
    const unsigned myxs = smbase + (XS + warp * NBUF * WXB) * 4;
    const unsigned mymb = smbase + MBAR_F * 4 + warp * NBUF * 8;

    if (tid == 0) {
        #pragma unroll
        for (int i = 0; i < NWARP * NBUF; i++)
            MB_INIT(smbase + MBAR_F * 4 + 8 * i, 1);
    }
    __syncthreads();

    if (lane == 0) {
        #pragma unroll
        for (int b = 0; b < NBUF; b++) {
            MB_EXPECT_TX(mymb + 8 * b, WXB * 4);
            TMA_2D(myxs + b * WXB * 4, &tmap, b * KC, wrow0, mymb + 8 * b);
        }
    }

    unsigned long long acc[4][4];
    #pragma unroll
    for (int i = 0; i < 4; i++)
        #pragma unroll
        for (int jj = 0; jj < 4; jj++) acc[i][jj] = 0ull;

    const float* wgbase = g_Wq + cg * 4;
    const float* myxf = sm + XS + warp * NBUF * WXB;

    int buf = 0, ph = 0;
    for (int c = 0; c < NCHUNK; c++) {
        MB_WAIT(mymb + 8 * buf, ph);

        const float* xb = myxf + buf * WXB;
        const float* wc = wgbase + c * (NKQ * DM * 4);
        #pragma unroll
        for (int kq = 0; kq < NKQ; kq++) {
            ulonglong2 wv[4];
            #pragma unroll
            for (int jj = 0; jj < 4; jj++)
                wv[jj] = __ldg((const ulonglong2*)(wc + kq * (DM * 4) + jj * 16));
            ulonglong2 xv[4];
            #pragma unroll
            for (int i = 0; i < 4; i++)
                xv[i] = *(const ulonglong2*)(xb + (rs + 8 * i) * KC + kq * 4);
            #pragma unroll
            for (int i = 0; i < 4; i++)
                #pragma unroll
                for (int jj = 0; jj < 4; jj++) {
                    fma2(acc[i][jj], xv[i].x, wv[jj].x);
                    fma2(acc[i][jj], xv[i].y, wv[jj].y);
                }
        }
        // refill this warp's buffer for chunk c+NBUF (intra-warp order makes
        // this safe: all LDS of buf are consumed by the fma2 chain above)
        if (c + NBUF < NCHUNK && lane == 0) {
            MB_EXPECT_TX(mymb + 8 * buf, WXB * 4);
            TMA_2D(myxs + buf * WXB * 4, &tmap, (c + NBUF) * KC, wrow0, mymb + 8 * buf);
        }
        if (++buf == NBUF) { buf = 0; ph ^= 1; }
    }

    // ---- reduce f32x2 accs into dedicated hx tile ----
    #pragma unroll
    for (int i = 0; i < 4; i++) {
        int row = warp * WROWS + rs + 8 * i;
        #pragma unroll
        for (int jj = 0; jj < 4; jj++)
            sm[HXS + row * 17 + jj * 4 + cg] = red2(acc[i][jj]);
    }
    __syncthreads();

    // ---- phase 2: exactly one row per thread ----
    {
        float hx[DM];
        #pragma unroll
        for (int j = 0; j < DM; j++) hx[j] = sm[HXS + tid * 17 + j];

        const long long grow  = row0 + tid;
        const long long hbase = (long long)batch * NC;
        const long long hblk  = (long long)batch * HID;

        #pragma unroll
        for (int ib = 0; ib < NB; ib++) {
            float h[HID];
            #pragma unroll
            for (int a = 0; a < HID; a++) {
                const float4* lp = (const float4*)(Lw + ib * (HID * DM) + a * DM);
                const float4* rp = (const float4*)(Rw + ib * (HID * DM) + a * DM);
                float su = 0.f, sv = 0.f;
                #pragma unroll
                for (int q = 0; q < 4; q++) {
                    float4 l4 = __ldg(lp + q), r4 = __ldg(rp + q);
                    su = fmaf(l4.x, hx[q*4+0], fmaf(l4.y, hx[q*4+1],
                         fmaf(l4.z, hx[q*4+2], fmaf(l4.w, hx[q*4+3], su))));
                    sv = fmaf(r4.x, hx[q*4+0], fmaf(r4.y, hx[q*4+1],
                         fmaf(r4.z, hx[q*4+2], fmaf(r4.w, hx[q*4+3], sv))));
                }
                h[a] = su * sv;
            }
            {
                float* hp = out + hbase + (long long)ib * hblk + grow * HID;
                *(float2*)(hp + 0) = make_float2(h[0], h[1]);
                *(float2*)(hp + 2) = make_float2(h[2], h[3]);
                *(float2*)(hp + 4) = make_float2(h[4], h[5]);
            }
            #pragma unroll
            for (int a = 0; a < HID; a++) {
                const float4* dp = (const float4*)(g_Dt + ib * (DM * HID) + a * DM);
                #pragma unroll
                for (int q = 0; q < 4; q++) {
                    float4 d4 = dp[q];
                    hx[q*4+0] = fmaf(h[a], d4.x, hx[q*4+0]);
                    hx[q*4+1] = fmaf(h[a], d4.y, hx[q*4+1]);
                    hx[q*4+2] = fmaf(h[a], d4.z, hx[q*4+2]);
                    hx[q*4+3] = fmaf(h[a], d4.w, hx[q*4+3]);
                }
            }
        }

        float lg[NC];
        #pragma unroll
        for (int cc = 0; cc < NC; cc++) {
            const float4* wp = (const float4*)(Wh + cc * DM);
            float s = 0.f;
            #pragma unroll
            for (int q = 0; q < 4; q++) {
                float4 w4 = __ldg(wp + q);
                s = fmaf(w4.x, hx[q*4+0], fmaf(w4.y, hx[q*4+1],
                    fmaf(w4.z, hx[q*4+2], fmaf(w4.w, hx[q*4+3], s))));
            }
            lg[cc] = s;
        }
        float* op = out + grow * NC;
        *(float2*)(op + 0) = make_float2(lg[0], lg[1]);
        *(float2*)(op + 2) = make_float2(lg[2], lg[3]);
        *(float2*)(op + 4) = make_float2(lg[4], lg[5]);
        *(float2*)(op + 6) = make_float2(lg[6], lg[7]);
        *(float2*)(op + 8) = make_float2(lg[8], lg[9]);
    }
}

typedef CUresult (*PFN_encodeTiled)(
    CUtensorMap*, CUtensorMapDataType, cuuint32_t, void*,
    const cuuint64_t*, const cuuint64_t*, const cuuint32_t*, const cuuint32_t*,
    CUtensorMapInterleave, CUtensorMapSwizzle, CUtensorMapL2promotion,
    CUtensorMapFloatOOBfill);

extern "C" void kernel_launch(void* const* d_in, const int* in_sizes, int n_in,
                              void* d_out, int out_size)
{
    const float* x  = (const float*)d_in[0];
    const float* We = (const float*)d_in[1];
    const float* Lw = (const float*)d_in[2];
    const float* Rw = (const float*)d_in[3];
    const float* Dw = (const float*)d_in[4];
    const float* Wh = (const float*)d_in[5];
    float* out = (float*)d_out;

    int batch = in_sizes[0] / IN_DIM;   // 65536
    int grid  = batch / TROWS;          // 512

    CUtensorMap tmap;
    {
        void* fp = nullptr;
        cudaDriverEntryPointQueryResult st;
        cudaGetDriverEntryPoint("cuTensorMapEncodeTiled", &fp,
                                cudaEnableDefault, &st);
        PFN_encodeTiled enc = (PFN_encodeTiled)fp;
        cuuint64_t dims[2]    = {IN_DIM, (cuuint64_t)batch};
        cuuint64_t strides[1] = {IN_DIM * sizeof(float)};
        cuuint32_t box[2]     = {KC, WROWS};
        cuuint32_t estr[2]    = {1, 1};
        enc(&tmap, CU_TENSOR_MAP_DATA_TYPE_FLOAT32, 2, (void*)x,
            dims, strides, box, estr,
            CU_TENSOR_MAP_INTERLEAVE_NONE, CU_TENSOR_MAP_SWIZZLE_NONE,
            CU_TENSOR_MAP_L2_PROMOTION_L2_128B, CU_TENSOR_MAP_FLOAT_OOB_FILL_NONE);
    }

    reorder_kernel<<<(DM * IN_DIM + 255) / 256, 256>>>(We, Dw);

    size_t smem = (size_t)SMEM_FLOATS * sizeof(float);   // ~50.6 KB
    cudaFuncSetAttribute(bilinear_resnet_kernel,
                         cudaFuncAttributeMaxDynamicSharedMemorySize, (int)smem);
    bilinear_resnet_kernel<<<grid, NTH, smem>>>(tmap, Lw, Rw, Wh, out, batch);
}

// round 14
// speedup vs baseline: 1.5934x; 1.5934x over previous
#include <cuda_runtime.h>
#include <cuda.h>

// BilinearResNet fused, GB300 sm_103a — round 14
// Embed GEMM via mma.sync m16n8k8 tf32 (3xTF32 split for fp32-grade accuracy).
// x: TMA SW128 tiles (32 floats x 128 rows), ring-3 (round-11 proven pipeline).
// W: pre-split hi/lo, reordered [k][n] in global, coalesced LDG.
// A-frags: conflict-free LDS.32 from swizzled smem. Phase 2 unchanged.

#define IN_DIM 784
#define DM     16
#define HID    6
#define NB     4
#define NC     10
#define KC     32            // floats per k-chunk (128B rows, SW128)
#define NCH    25            // 25*32 = 800 >= 784, OOB zero-filled
#define TROWS  128
#define NTH    128
#define NBUF   3
#define XCHB   16384         // bytes per x buffer (128 rows x 128B)
#define BAR_B  (NBUF*XCHB)   // 49152
#define SMEM_BYTES (BAR_B + 32)
#define NW     (NCH*4*8*DM)  // 12800 floats per W array

// reordered weights in global (written by pre-kernel)
__device__ __align__(16) float g_Wh[NW];            // [k8step][kk][n] hi part
__device__ __align__(16) float g_Wl[NW];            // lo part
__device__ __align__(16) float g_Dt[NB * DM * HID]; // [i][a][j]

__global__ void reorder_kernel(const float* __restrict__ We,
                               const float* __restrict__ Dw) {
    int idx = blockIdx.x * 256 + threadIdx.x;
    if (idx < NW) {
        int n = idx & 15;
        int k = idx >> 4;            // 0..799
        float w = (k < IN_DIM) ? We[n * IN_DIM + k] : 0.f;
        unsigned hb = __float_as_uint(w) & 0xFFFFE000u;
        float fh = __uint_as_float(hb);
        g_Wh[idx] = fh;
        g_Wl[idx] = w - fh;
    }
    if (idx < NB * DM * HID) {
        int i = idx / (DM * HID), r = idx % (DM * HID);
        int j = r / HID, a = r % HID;
        g_Dt[i * (DM * HID) + a * DM + j] = Dw[idx];
    }
}

#define MMA(cc, a0, a1, a2, a3, b0, b1) \
    asm volatile("mma.sync.aligned.m16n8k8.row.col.f32.tf32.tf32.f32 " \
        "{%0,%1,%2,%3}, {%4,%5,%6,%7}, {%8,%9}, {%0,%1,%2,%3};" \
        : "+f"((cc)[0]), "+f"((cc)[1]), "+f"((cc)[2]), "+f"((cc)[3]) \
        : "r"(a0), "r"(a1), "r"(a2), "r"(a3), "r"(b0), "r"(b1))

#define MB_INIT(addr, cnt) \
    asm volatile("mbarrier.init.shared.b64 [%0], %1;" :: "r"(addr), "r"(cnt) : "memory")
#define MB_EXPECT_TX(addr, bytes) \
    asm volatile("mbarrier.arrive.expect_tx.shared.b64 _, [%0], %1;" :: "r"(addr), "r"(bytes) : "memory")
#define MB_WAIT(addr, parity) do {                                                  \
    asm volatile("{\n\t.reg .pred P;\n"                                             \
        "WLP%=:\n\tmbarrier.try_wait.parity.acquire.cta.shared::cta.b64 P, [%0], %1, 0x989680;\n" \
        "\t@P bra WDN%=;\n\tbra WLP%=;\nWDN%=:\n\t}"                                \
        :: "r"(addr), "r"(parity) : "memory"); } while (0)
#define TMA_2D(dst, tmapp, cx, cy, mb)                                              \
    asm volatile("cp.async.bulk.tensor.2d.shared::cta.global.tile.mbarrier::complete_tx::bytes " \
        "[%0], [%1, {%2, %3}], [%4];"                                               \
        :: "r"(dst), "l"(tmapp), "r"(cx), "r"(cy), "r"(mb) : "memory")

__global__ __launch_bounds__(NTH, 4)
void bilinear_resnet_kernel(const __grid_constant__ CUtensorMap tmap,
                            const float* __restrict__ Lw,
                            const float* __restrict__ Rw,
                            const float* __restrict__ Wh,
                            float* __restrict__ out,
                            int batch)
{
    extern __shared__ char smc[];
    float* smf = (float*)smc;
    const int tid = threadIdx.x;
    const unsigned smbase = (unsigned)__cvta_generic_to_shared(smc);
    const unsigned mbB = smbase + BAR_B;
    const int row0 = blockIdx.x * TROWS;

    const int warp = tid >> 5, lane = tid & 31;
    const int g  = lane >> 2;       // groupID 0..7
    const int tg = lane & 3;        // thread-in-group 0..3
    const int w32 = warp * 32;      // warp row base within tile
    const unsigned xorg = (unsigned)(g << 4);   // SW128 swizzle for this lane's rows

    if (tid == 0) {
        #pragma unroll
        for (int b = 0; b < NBUF; b++) MB_INIT(mbB + 8 * b, 1);
    }
    __syncthreads();

    if (tid == 0) {
        #pragma unroll
        for (int b = 0; b < NBUF; b++) {
            MB_EXPECT_TX(mbB + 8 * b, XCHB);
            TMA_2D(smbase + b * XCHB, &tmap, b * KC, row0, mbB + 8 * b);
        }
    }

    // accumulators: [tile 0/1][n-block 0/1][4]
    float acc[2][2][4];
    #pragma unroll
    for (int t = 0; t < 2; t++)
        #pragma unroll
        for (int m = 0; m < 2; m++)
            #pragma unroll
            for (int q = 0; q < 4; q++) acc[t][m][q] = 0.f;

    int buf = 0, ph = 0;
    for (int c = 0; c < NCH; c++) {
        MB_WAIT(mbB + 8 * buf, ph);
        const char* xb = smc + buf * XCHB;

        #pragma unroll
        for (int s = 0; s < 4; s++) {
            // B fragments (W) for this k8-step: hi and lo, n-blocks 0 and 1
            const int bsO = (c * 4 + s) * 128 + tg * 16 + g;
            unsigned bh[2][2], bl[2][2];
            #pragma unroll
            for (int m = 0; m < 2; m++) {
                bh[m][0] = __float_as_uint(__ldg(g_Wh + bsO + m * 8));
                bh[m][1] = __float_as_uint(__ldg(g_Wh + bsO + m * 8 + 64));
                bl[m][0] = __float_as_uint(__ldg(g_Wl + bsO + m * 8));
                bl[m][1] = __float_as_uint(__ldg(g_Wl + bsO + m * 8 + 64));
            }

            const int koff = (s * 8 + tg) * 4;   // bytes within 128B row
            #pragma unroll
            for (int t = 0; t < 2; t++) {
                const unsigned off0 = (unsigned)((w32 + t * 16 + g) * 128 + koff);
                unsigned a0 = *(const unsigned*)(xb + ((off0       ) ^ xorg));
                unsigned a1 = *(const unsigned*)(xb + ((off0 + 1024) ^ xorg));
                unsigned a2 = *(const unsigned*)(xb + ((off0 +   16) ^ xorg));
                unsigned a3 = *(const unsigned*)(xb + ((off0 + 1040) ^ xorg));
                // split hi/lo (exact)
                unsigned h0 = a0 & 0xFFFFE000u, h1 = a1 & 0xFFFFE000u;
                unsigned h2 = a2 & 0xFFFFE000u, h3 = a3 & 0xFFFFE000u;
                unsigned l0 = __float_as_uint(__uint_as_float(a0) - __uint_as_float(h0));
                unsigned l1 = __float_as_uint(__uint_as_float(a1) - __uint_as_float(h1));
                unsigned l2 = __float_as_uint(__uint_as_float(a2) - __uint_as_float(h2));
                unsigned l3 = __float_as_uint(__uint_as_float(a3) - __uint_as_float(h3));
                #pragma unroll
                for (int m = 0; m < 2; m++) {
                    MMA(acc[t][m], h0, h1, h2, h3, bh[m][0], bh[m][1]);
                    MMA(acc[t][m], l0, l1, l2, l3, bh[m][0], bh[m][1]);
                    MMA(acc[t][m], h0, h1, h2, h3, bl[m][0], bl[m][1]);
                }
            }
        }

        __syncthreads();   // all warps done reading buf
        if (c + NBUF < NCH && tid == 0) {
            MB_EXPECT_TX(mbB + 8 * buf, XCHB);
            TMA_2D(smbase + buf * XCHB, &tmap, (c + NBUF) * KC, row0, mbB + 8 * buf);
        }
        if (++buf == NBUF) { buf = 0; ph ^= 1; }
    }

    // ---- scatter C fragments into hx tile (aliases buf0; safe after last sync) ----
    #pragma unroll
    for (int t = 0; t < 2; t++) {
        const int r0 = w32 + t * 16 + g;
        #pragma unroll
        for (int m = 0; m < 2; m++) {
            const int cb = m * 8 + tg * 2;
            smf[r0 * 17 + cb]           = acc[t][m][0];
            smf[r0 * 17 + cb + 1]       = acc[t][m][1];
            smf[(r0 + 8) * 17 + cb]     = acc[t][m][2];
            smf[(r0 + 8) * 17 + cb + 1] = acc[t][m][3];
        }
    }
    __syncthreads();

    // ---- phase 2: exactly one row per thread ----
    {
        float hx[DM];
        #pragma unroll
        for (int j = 0; j < DM; j++) hx[j] = smf[tid * 17 + j];

        const long long grow  = row0 + tid;
        const long long hbase = (long long)batch * NC;
        const long long hblk  = (long long)batch * HID;

        #pragma unroll
        for (int ib = 0; ib < NB; ib++) {
            float h[HID];
            #pragma unroll
            for (int a = 0; a < HID; a++) {
                const float4* lp = (const float4*)(Lw + ib * (HID * DM) + a * DM);
                const float4* rp = (const float4*)(Rw + ib * (HID * DM) + a * DM);
                float su = 0.f, sv = 0.f;
                #pragma unroll
                for (int q = 0; q < 4; q++) {
                    float4 l4 = __ldg(lp + q), r4 = __ldg(rp + q);
                    su = fmaf(l4.x, hx[q*4+0], fmaf(l4.y, hx[q*4+1],
                         fmaf(l4.z, hx[q*4+2], fmaf(l4.w, hx[q*4+3], su))));
                    sv = fmaf(r4.x, hx[q*4+0], fmaf(r4.y, hx[q*4+1],
                         fmaf(r4.z, hx[q*4+2], fmaf(r4.w, hx[q*4+3], sv))));
                }
                h[a] = su * sv;
            }
            {
                float* hp = out + hbase + (long long)ib * hblk + grow * HID;
                *(float2*)(hp + 0) = make_float2(h[0], h[1]);
                *(float2*)(hp + 2) = make_float2(h[2], h[3]);
                *(float2*)(hp + 4) = make_float2(h[4], h[5]);
            }
            #pragma unroll
            for (int a = 0; a < HID; a++) {
                const float4* dp = (const float4*)(g_Dt + ib * (DM * HID) + a * DM);
                #pragma unroll
                for (int q = 0; q < 4; q++) {
                    float4 d4 = dp[q];
                    hx[q*4+0] = fmaf(h[a], d4.x, hx[q*4+0]);
                    hx[q*4+1] = fmaf(h[a], d4.y, hx[q*4+1]);
                    hx[q*4+2] = fmaf(h[a], d4.z, hx[q*4+2]);
                    hx[q*4+3] = fmaf(h[a], d4.w, hx[q*4+3]);
                }
            }
        }

        float lg[NC];
        #pragma unroll
        for (int cc = 0; cc < NC; cc++) {
            const float4* wp = (const float4*)(Wh + cc * DM);
            float s = 0.f;
            #pragma unroll
            for (int q = 0; q < 4; q++) {
                float4 w4 = __ldg(wp + q);
                s = fmaf(w4.x, hx[q*4+0], fmaf(w4.y, hx[q*4+1],
                    fmaf(w4.z, hx[q*4+2], fmaf(w4.w, hx[q*4+3], s))));
            }
            lg[cc] = s;
        }
        float* op = out + grow * NC;
        *(float2*)(op + 0) = make_float2(lg[0], lg[1]);
        *(float2*)(op + 2) = make_float2(lg[2], lg[3]);
        *(float2*)(op + 4) = make_float2(lg[4], lg[5]);
        *(float2*)(op + 6) = make_float2(lg[6], lg[7]);
        *(float2*)(op + 8) = make_float2(lg[8], lg[9]);
    }
}

typedef CUresult (*PFN_encodeTiled)(
    CUtensorMap*, CUtensorMapDataType, cuuint32_t, void*,
    const cuuint64_t*, const cuuint64_t*, const cuuint32_t*, const cuuint32_t*,
    CUtensorMapInterleave, CUtensorMapSwizzle, CUtensorMapL2promotion,
    CUtensorMapFloatOOBfill);

extern "C" void kernel_launch(void* const* d_in, const int* in_sizes, int n_in,
                              void* d_out, int out_size)
{
    const float* x  = (const float*)d_in[0];
    const float* We = (const float*)d_in[1];
    const float* Lw = (const float*)d_in[2];
    const float* Rw = (const float*)d_in[3];
    const float* Dw = (const float*)d_in[4];
    const float* Wh = (const float*)d_in[5];
    float* out = (float*)d_out;

    int batch = in_sizes[0] / IN_DIM;   // 65536
    int grid  = batch / TROWS;          // 512

    // x tensor map: [784, batch] fp32, box [32, 128], SW128, OOB -> zero
    CUtensorMap tmap;
    {
        void* fp = nullptr;
        cudaDriverEntryPointQueryResult st;
        cudaGetDriverEntryPoint("cuTensorMapEncodeTiled", &fp,
                                cudaEnableDefault, &st);
        PFN_encodeTiled enc = (PFN_encodeTiled)fp;
        cuuint64_t dims[2]    = {IN_DIM, (cuuint64_t)batch};
        cuuint64_t strides[1] = {IN_DIM * sizeof(float)};
        cuuint32_t box[2]     = {KC, TROWS};
        cuuint32_t estr[2]    = {1, 1};
        enc(&tmap, CU_TENSOR_MAP_DATA_TYPE_FLOAT32, 2, (void*)x,
            dims, strides, box, estr,
            CU_TENSOR_MAP_INTERLEAVE_NONE, CU_TENSOR_MAP_SWIZZLE_128B,
            CU_TENSOR_MAP_L2_PROMOTION_L2_128B, CU_TENSOR_MAP_FLOAT_OOB_FILL_NONE);
    }

    reorder_kernel<<<(NW + 255) / 256, 256>>>(We, Dw);

    cudaFuncSetAttribute(bilinear_resnet_kernel,
                         cudaFuncAttributeMaxDynamicSharedMemorySize, SMEM_BYTES);
    bilinear_resnet_kernel<<<grid, NTH, SMEM_BYTES>>>(tmap, Lw, Rw, Wh, out, batch);
}

// round 15
// speedup vs baseline: 1.7158x; 1.0768x over previous
#include <cuda_runtime.h>
#include <cuda.h>

// BilinearResNet fused, GB300 sm_103a — round 15
// Round-14 mma.sync tf32 (3xTF32) kernel with small tiles for occupancy:
// TROWS=64/NTH=64/grid=1024, 8 CTAs/SM, NBUF=2 ring (16.4KB smem/CTA).

#define IN_DIM 784
#define DM     16
#define HID    6
#define NB     4
#define NC     10
#define KC     32            // floats per k-chunk (128B rows, SW128)
#define NCH    25            // 25*32 = 800 >= 784, OOB zero-filled
#define TROWS  64
#define NTH    64
#define NBUF   2
#define XCHB   8192          // bytes per x buffer (64 rows x 128B)
#define BAR_B  (NBUF*XCHB)   // 16384
#define SMEM_BYTES (BAR_B + 32)
#define NW     (NCH*4*8*DM)  // 12800 floats per W array

// reordered weights in global (written by pre-kernel)
__device__ __align__(16) float g_Wh[NW];            // [k8step][kk][n] hi part
__device__ __align__(16) float g_Wl[NW];            // lo part
__device__ __align__(16) float g_Dt[NB * DM * HID]; // [i][a][j]

__global__ void reorder_kernel(const float* __restrict__ We,
                               const float* __restrict__ Dw) {
    int idx = blockIdx.x * 256 + threadIdx.x;
    if (idx < NW) {
        int n = idx & 15;
        int k = idx >> 4;            // 0..799
        float w = (k < IN_DIM) ? We[n * IN_DIM + k] : 0.f;
        unsigned hb = __float_as_uint(w) & 0xFFFFE000u;
        float fh = __uint_as_float(hb);
        g_Wh[idx] = fh;
        g_Wl[idx] = w - fh;
    }
    if (idx < NB * DM * HID) {
        int i = idx / (DM * HID), r = idx % (DM * HID);
        int j = r / HID, a = r % HID;
        g_Dt[i * (DM * HID) + a * DM + j] = Dw[idx];
    }
}

#define MMA(cc, a0, a1, a2, a3, b0, b1) \
    asm volatile("mma.sync.aligned.m16n8k8.row.col.f32.tf32.tf32.f32 " \
        "{%0,%1,%2,%3}, {%4,%5,%6,%7}, {%8,%9}, {%0,%1,%2,%3};" \
        : "+f"((cc)[0]), "+f"((cc)[1]), "+f"((cc)[2]), "+f"((cc)[3]) \
        : "r"(a0), "r"(a1), "r"(a2), "r"(a3), "r"(b0), "r"(b1))

#define MB_INIT(addr, cnt) \
    asm volatile("mbarrier.init.shared.b64 [%0], %1;" :: "r"(addr), "r"(cnt) : "memory")
#define MB_EXPECT_TX(addr, bytes) \
    asm volatile("mbarrier.arrive.expect_tx.shared.b64 _, [%0], %1;" :: "r"(addr), "r"(bytes) : "memory")
#define MB_WAIT(addr, parity) do {                                                  \
    asm volatile("{\n\t.reg .pred P;\n"                                             \
        "WLP%=:\n\tmbarrier.try_wait.parity.acquire.cta.shared::cta.b64 P, [%0], %1, 0x989680;\n" \
        "\t@P bra WDN%=;\n\tbra WLP%=;\nWDN%=:\n\t}"                                \
        :: "r"(addr), "r"(parity) : "memory"); } while (0)
#define TMA_2D(dst, tmapp, cx, cy, mb)                                              \
    asm volatile("cp.async.bulk.tensor.2d.shared::cta.global.tile.mbarrier::complete_tx::bytes " \
        "[%0], [%1, {%2, %3}], [%4];"                                               \
        :: "r"(dst), "l"(tmapp), "r"(cx), "r"(cy), "r"(mb) : "memory")

__global__ __launch_bounds__(NTH, 8)
void bilinear_resnet_kernel(const __grid_constant__ CUtensorMap tmap,
                            const float* __restrict__ Lw,
                            const float* __restrict__ Rw,
                            const float* __restrict__ Wh,
                            float* __restrict__ out,
                            int batch)
{
    extern __shared__ char smc[];
    float* smf = (float*)smc;
    const int tid = threadIdx.x;
    const unsigned smbase = (unsigned)__cvta_generic_to_shared(smc);
    const unsigned mbB = smbase + BAR_B;
    const int row0 = blockIdx.x * TROWS;

    const int warp = tid >> 5, lane = tid & 31;
    const int g  = lane >> 2;       // groupID 0..7
    const int tg = lane & 3;        // thread-in-group 0..3
    const int w32 = warp * 32;      // warp row base within tile
    const unsigned xorg = (unsigned)(g << 4);   // SW128 swizzle for this lane's rows

    if (tid == 0) {
        #pragma unroll
        for (int b = 0; b < NBUF; b++) MB_INIT(mbB + 8 * b, 1);
    }
    __syncthreads();

    if (tid == 0) {
        #pragma unroll
        for (int b = 0; b < NBUF; b++) {
            MB_EXPECT_TX(mbB + 8 * b, XCHB);
            TMA_2D(smbase + b * XCHB, &tmap, b * KC, row0, mbB + 8 * b);
        }
    }

    // accumulators: [tile 0/1][n-block 0/1][4]
    float acc[2][2][4];
    #pragma unroll
    for (int t = 0; t < 2; t++)
        #pragma unroll
        for (int m = 0; m < 2; m++)
            #pragma unroll
            for (int q = 0; q < 4; q++) acc[t][m][q] = 0.f;

    int buf = 0, ph = 0;
    for (int c = 0; c < NCH; c++) {
        MB_WAIT(mbB + 8 * buf, ph);
        const char* xb = smc + buf * XCHB;

        #pragma unroll
        for (int s = 0; s < 4; s++) {
            // B fragments (W) for this k8-step: hi and lo, n-blocks 0 and 1
            const int bsO = (c * 4 + s) * 128 + tg * 16 + g;
            unsigned bh[2][2], bl[2][2];
            #pragma unroll
            for (int m = 0; m < 2; m++) {
                bh[m][0] = __float_as_uint(__ldg(g_Wh + bsO + m * 8));
                bh[m][1] = __float_as_uint(__ldg(g_Wh + bsO + m * 8 + 64));
                bl[m][0] = __float_as_uint(__ldg(g_Wl + bsO + m * 8));
                bl[m][1] = __float_as_uint(__ldg(g_Wl + bsO + m * 8 + 64));
            }

            const int koff = (s * 8 + tg) * 4;   // bytes within 128B row
            #pragma unroll
            for (int t = 0; t < 2; t++) {
                const unsigned off0 = (unsigned)((w32 + t * 16 + g) * 128 + koff);
                unsigned a0 = *(const unsigned*)(xb + ((off0       ) ^ xorg));
                unsigned a1 = *(const unsigned*)(xb + ((off0 + 1024) ^ xorg));
                unsigned a2 = *(const unsigned*)(xb + ((off0 +   16) ^ xorg));
                unsigned a3 = *(const unsigned*)(xb + ((off0 + 1040) ^ xorg));
                // split hi/lo (exact)
                unsigned h0 = a0 & 0xFFFFE000u, h1 = a1 & 0xFFFFE000u;
                unsigned h2 = a2 & 0xFFFFE000u, h3 = a3 & 0xFFFFE000u;
                unsigned l0 = __float_as_uint(__uint_as_float(a0) - __uint_as_float(h0));
                unsigned l1 = __float_as_uint(__uint_as_float(a1) - __uint_as_float(h1));
                unsigned l2 = __float_as_uint(__uint_as_float(a2) - __uint_as_float(h2));
                unsigned l3 = __float_as_uint(__uint_as_float(a3) - __uint_as_float(h3));
                #pragma unroll
                for (int m = 0; m < 2; m++) {
                    MMA(acc[t][m], h0, h1, h2, h3, bh[m][0], bh[m][1]);
                    MMA(acc[t][m], l0, l1, l2, l3, bh[m][0], bh[m][1]);
                    MMA(acc[t][m], h0, h1, h2, h3, bl[m][0], bl[m][1]);
                }
            }
        }

        __syncthreads();   // all warps done reading buf
        if (c + NBUF < NCH && tid == 0) {
            MB_EXPECT_TX(mbB + 8 * buf, XCHB);
            TMA_2D(smbase + buf * XCHB, &tmap, (c + NBUF) * KC, row0, mbB + 8 * buf);
        }
        if (++buf == NBUF) { buf = 0; ph ^= 1; }
    }

    // ---- scatter C fragments into hx tile (aliases buf0; safe after last sync) ----
    #pragma unroll
    for (int t = 0; t < 2; t++) {
        const int r0 = w32 + t * 16 + g;
        #pragma unroll
        for (int m = 0; m < 2; m++) {
            const int cb = m * 8 + tg * 2;
            smf[r0 * 17 + cb]           = acc[t][m][0];
            smf[r0 * 17 + cb + 1]       = acc[t][m][1];
            smf[(r0 + 8) * 17 + cb]     = acc[t][m][2];
            smf[(r0 + 8) * 17 + cb + 1] = acc[t][m][3];
        }
    }
    __syncthreads();

    // ---- phase 2: exactly one row per thread ----
    {
        float hx[DM];
        #pragma unroll
        for (int j = 0; j < DM; j++) hx[j] = smf[tid * 17 + j];

        const long long grow  = row0 + tid;
        const long long hbase = (long long)batch * NC;
        const long long hblk  = (long long)batch * HID;

        #pragma unroll
        for (int ib = 0; ib < NB; ib++) {
            float h[HID];
            #pragma unroll
            for (int a = 0; a < HID; a++) {
                const float4* lp = (const float4*)(Lw + ib * (HID * DM) + a * DM);
                const float4* rp = (const float4*)(Rw + ib * (HID * DM) + a * DM);
                float su = 0.f, sv = 0.f;
                #pragma unroll
                for (int q = 0; q < 4; q++) {
                    float4 l4 = __ldg(lp + q), r4 = __ldg(rp + q);
                    su = fmaf(l4.x, hx[q*4+0], fmaf(l4.y, hx[q*4+1],
                         fmaf(l4.z, hx[q*4+2], fmaf(l4.w, hx[q*4+3], su))));
                    sv = fmaf(r4.x, hx[q*4+0], fmaf(r4.y, hx[q*4+1],
                         fmaf(r4.z, hx[q*4+2], fmaf(r4.w, hx[q*4+3], sv))));
                }
                h[a] = su * sv;
            }
            {
                float* hp = out + hbase + (long long)ib * hblk + grow * HID;
                *(float2*)(hp + 0) = make_float2(h[0], h[1]);
                *(float2*)(hp + 2) = make_float2(h[2], h[3]);
                *(float2*)(hp + 4) = make_float2(h[4], h[5]);
            }
            #pragma unroll
            for (int a = 0; a < HID; a++) {
                const float4* dp = (const float4*)(g_Dt + ib * (DM * HID) + a * DM);
                #pragma unroll
                for (int q = 0; q < 4; q++) {
                    float4 d4 = dp[q];
                    hx[q*4+0] = fmaf(h[a], d4.x, hx[q*4+0]);
                    hx[q*4+1] = fmaf(h[a], d4.y, hx[q*4+1]);
                    hx[q*4+2] = fmaf(h[a], d4.z, hx[q*4+2]);
                    hx[q*4+3] = fmaf(h[a], d4.w, hx[q*4+3]);
                }
            }
        }

        float lg[NC];
        #pragma unroll
        for (int cc = 0; cc < NC; cc++) {
            const float4* wp = (const float4*)(Wh + cc * DM);
            float s = 0.f;
            #pragma unroll
            for (int q = 0; q < 4; q++) {
                float4 w4 = __ldg(wp + q);
                s = fmaf(w4.x, hx[q*4+0], fmaf(w4.y, hx[q*4+1],
                    fmaf(w4.z, hx[q*4+2], fmaf(w4.w, hx[q*4+3], s))));
            }
            lg[cc] = s;
        }
        float* op = out + grow * NC;
        *(float2*)(op + 0) = make_float2(lg[0], lg[1]);
        *(float2*)(op + 2) = make_float2(lg[2], lg[3]);
        *(float2*)(op + 4) = make_float2(lg[4], lg[5]);
        *(float2*)(op + 6) = make_float2(lg[6], lg[7]);
        *(float2*)(op + 8) = make_float2(lg[8], lg[9]);
    }
}

typedef CUresult (*PFN_encodeTiled)(
    CUtensorMap*, CUtensorMapDataType, cuuint32_t, void*,
    const cuuint64_t*, const cuuint64_t*, const cuuint32_t*, const cuuint32_t*,
    CUtensorMapInterleave, CUtensorMapSwizzle, CUtensorMapL2promotion,
    CUtensorMapFloatOOBfill);

extern "C" void kernel_launch(void* const* d_in, const int* in_sizes, int n_in,
                              void* d_out, int out_size)
{
    const float* x  = (const float*)d_in[0];
    const float* We = (const float*)d_in[1];
    const float* Lw = (const float*)d_in[2];
    const float* Rw = (const float*)d_in[3];
    const float* Dw = (const float*)d_in[4];
    const float* Wh = (const float*)d_in[5];
    float* out = (float*)d_out;

    int batch = in_sizes[0] / IN_DIM;   // 65536
    int grid  = batch / TROWS;          // 1024

    // x tensor map: [784, batch] fp32, box [32, 64], SW128, OOB -> zero
    CUtensorMap tmap;
    {
        void* fp = nullptr;
        cudaDriverEntryPointQueryResult st;
        cudaGetDriverEntryPoint("cuTensorMapEncodeTiled", &fp,
                                cudaEnableDefault, &st);
        PFN_encodeTiled enc = (PFN_encodeTiled)fp;
        cuuint64_t dims[2]    = {IN_DIM, (cuuint64_t)batch};
        cuuint64_t strides[1] = {IN_DIM * sizeof(float)};
        cuuint32_t box[2]     = {KC, TROWS};
        cuuint32_t estr[2]    = {1, 1};
        enc(&tmap, CU_TENSOR_MAP_DATA_TYPE_FLOAT32, 2, (void*)x,
            dims, strides, box, estr,
            CU_TENSOR_MAP_INTERLEAVE_NONE, CU_TENSOR_MAP_SWIZZLE_128B,
            CU_TENSOR_MAP_L2_PROMOTION_L2_128B, CU_TENSOR_MAP_FLOAT_OOB_FILL_NONE);
    }

    reorder_kernel<<<(NW + 255) / 256, 256>>>(We, Dw);

    cudaFuncSetAttribute(bilinear_resnet_kernel,
                         cudaFuncAttributeMaxDynamicSharedMemorySize, SMEM_BYTES);
    bilinear_resnet_kernel<<<grid, NTH, SMEM_BYTES>>>(tmap, Lw, Rw, Wh, out, batch);
}

// round 16
// speedup vs baseline: 1.7217x; 1.0035x over previous
#include <cuda_runtime.h>
#include <cuda.h>

// BilinearResNet fused, GB300 sm_103a — round 16
// Round-15 geometry (TROWS=64/NTH=64/grid=1024, 8 CTAs/SM, NBUF=2 TMA ring)
// with 2-term tf32 split: D = Ah*B + Al*B, B = tf32(W) single 51KB array
// (L1-resident). 8 MMAs + 16 LDG per k8-step instead of 12 + 32.

#define IN_DIM 784
#define DM     16
#define HID    6
#define NB     4
#define NC     10
#define KC     32            // floats per k-chunk (128B rows, SW128)
#define NCH    25            // 25*32 = 800 >= 784, OOB zero-filled
#define TROWS  64
#define NTH    64
#define NBUF   2
#define XCHB   8192          // bytes per x buffer (64 rows x 128B)
#define BAR_B  (NBUF*XCHB)   // 16384
#define SMEM_BYTES (BAR_B + 32)
#define NW     (NCH*4*8*DM)  // 12800 floats

// reordered weights in global (written by pre-kernel)
__device__ __align__(16) float g_W[NW];             // [k8step][kk][n], tf32-rounded
__device__ __align__(16) float g_Dt[NB * DM * HID]; // [i][a][j]

__global__ void reorder_kernel(const float* __restrict__ We,
                               const float* __restrict__ Dw) {
    int idx = blockIdx.x * 256 + threadIdx.x;
    if (idx < NW) {
        int n = idx & 15;
        int k = idx >> 4;            // 0..799
        float w = (k < IN_DIM) ? We[n * IN_DIM + k] : 0.f;
        unsigned t;
        asm("cvt.rna.tf32.f32 %0, %1;" : "=r"(t) : "f"(w));
        g_W[idx] = __uint_as_float(t);
    }
    if (idx < NB * DM * HID) {
        int i = idx / (DM * HID), r = idx % (DM * HID);
        int j = r / HID, a = r % HID;
        g_Dt[i * (DM * HID) + a * DM + j] = Dw[idx];
    }
}

#define MMA(cc, a0, a1, a2, a3, b0, b1) \
    asm volatile("mma.sync.aligned.m16n8k8.row.col.f32.tf32.tf32.f32 " \
        "{%0,%1,%2,%3}, {%4,%5,%6,%7}, {%8,%9}, {%0,%1,%2,%3};" \
        : "+f"((cc)[0]), "+f"((cc)[1]), "+f"((cc)[2]), "+f"((cc)[3]) \
        : "r"(a0), "r"(a1), "r"(a2), "r"(a3), "r"(b0), "r"(b1))

#define MB_INIT(addr, cnt) \
    asm volatile("mbarrier.init.shared.b64 [%0], %1;" :: "r"(addr), "r"(cnt) : "memory")
#define MB_EXPECT_TX(addr, bytes) \
    asm volatile("mbarrier.arrive.expect_tx.shared.b64 _, [%0], %1;" :: "r"(addr), "r"(bytes) : "memory")
#define MB_WAIT(addr, parity) do {                                                  \
    asm volatile("{\n\t.reg .pred P;\n"                                             \
        "WLP%=:\n\tmbarrier.try_wait.parity.acquire.cta.shared::cta.b64 P, [%0], %1, 0x989680;\n" \
        "\t@P bra WDN%=;\n\tbra WLP%=;\nWDN%=:\n\t}"                                \
        :: "r"(addr), "r"(parity) : "memory"); } while (0)
#define TMA_2D(dst, tmapp, cx, cy, mb)                                              \
    asm volatile("cp.async.bulk.tensor.2d.shared::cta.global.tile.mbarrier::complete_tx::bytes " \
        "[%0], [%1, {%2, %3}], [%4];"                                               \
        :: "r"(dst), "l"(tmapp), "r"(cx), "r"(cy), "r"(mb) : "memory")

__global__ __launch_bounds__(NTH, 8)
void bilinear_resnet_kernel(const __grid_constant__ CUtensorMap tmap,
                            const float* __restrict__ Lw,
                            const float* __restrict__ Rw,
                            const float* __restrict__ Wh,
                            float* __restrict__ out,
                            int batch)
{
    extern __shared__ char smc[];
    float* smf = (float*)smc;
    const int tid = threadIdx.x;
    const unsigned smbase = (unsigned)__cvta_generic_to_shared(smc);
    const unsigned mbB = smbase + BAR_B;
    const int row0 = blockIdx.x * TROWS;

    const int warp = tid >> 5, lane = tid & 31;
    const int g  = lane >> 2;       // groupID 0..7
    const int tg = lane & 3;        // thread-in-group 0..3
    const int w32 = warp * 32;      // warp row base within tile
    const unsigned xorg = (unsigned)(g << 4);   // SW128 swizzle for this lane's rows

    if (tid == 0) {
        #pragma unroll
        for (int b = 0; b < NBUF; b++) MB_INIT(mbB + 8 * b, 1);
    }
    __syncthreads();

    if (tid == 0) {
        #pragma unroll
        for (int b = 0; b < NBUF; b++) {
            MB_EXPECT_TX(mbB + 8 * b, XCHB);
            TMA_2D(smbase + b * XCHB, &tmap, b * KC, row0, mbB + 8 * b);
        }
    }

    // accumulators: [tile 0/1][n-block 0/1][4]
    float acc[2][2][4];
    #pragma unroll
    for (int t = 0; t < 2; t++)
        #pragma unroll
        for (int m = 0; m < 2; m++)
            #pragma unroll
            for (int q = 0; q < 4; q++) acc[t][m][q] = 0.f;

    int buf = 0, ph = 0;
    for (int c = 0; c < NCH; c++) {
        MB_WAIT(mbB + 8 * buf, ph);
        const char* xb = smc + buf * XCHB;

        #pragma unroll
        for (int s = 0; s < 4; s++) {
            // B fragments (W, tf32-rounded) for this k8-step, n-blocks 0 and 1
            const int bsO = (c * 4 + s) * 128 + tg * 16 + g;
            unsigned bf[2][2];
            #pragma unroll
            for (int m = 0; m < 2; m++) {
                bf[m][0] = __float_as_uint(__ldg(g_W + bsO + m * 8));
                bf[m][1] = __float_as_uint(__ldg(g_W + bsO + m * 8 + 64));
            }

            const int koff = (s * 8 + tg) * 4;   // bytes within 128B row
            #pragma unroll
            for (int t = 0; t < 2; t++) {
                const unsigned off0 = (unsigned)((w32 + t * 16 + g) * 128 + koff);
                unsigned a0 = *(const unsigned*)(xb + ((off0       ) ^ xorg));
                unsigned a1 = *(const unsigned*)(xb + ((off0 + 1024) ^ xorg));
                unsigned a2 = *(const unsigned*)(xb + ((off0 +   16) ^ xorg));
                unsigned a3 = *(const unsigned*)(xb + ((off0 + 1040) ^ xorg));
                // exact split: x = Ah + Al (Ah is tf32-exact)
                unsigned h0 = a0 & 0xFFFFE000u, h1 = a1 & 0xFFFFE000u;
                unsigned h2 = a2 & 0xFFFFE000u, h3 = a3 & 0xFFFFE000u;
                unsigned l0 = __float_as_uint(__uint_as_float(a0) - __uint_as_float(h0));
                unsigned l1 = __float_as_uint(__uint_as_float(a1) - __uint_as_float(h1));
                unsigned l2 = __float_as_uint(__uint_as_float(a2) - __uint_as_float(h2));
                unsigned l3 = __float_as_uint(__uint_as_float(a3) - __uint_as_float(h3));
                #pragma unroll
                for (int m = 0; m < 2; m++) {
                    MMA(acc[t][m], h0, h1, h2, h3, bf[m][0], bf[m][1]);
                    MMA(acc[t][m], l0, l1, l2, l3, bf[m][0], bf[m][1]);
                }
            }
        }

        __syncthreads();   // all warps done reading buf
        if (c + NBUF < NCH && tid == 0) {
            MB_EXPECT_TX(mbB + 8 * buf, XCHB);
            TMA_2D(smbase + buf * XCHB, &tmap, (c + NBUF) * KC, row0, mbB + 8 * buf);
        }
        if (++buf == NBUF) { buf = 0; ph ^= 1; }
    }

    // ---- scatter C fragments into hx tile (aliases buf0; safe after last sync) ----
    #pragma unroll
    for (int t = 0; t < 2; t++) {
        const int r0 = w32 + t * 16 + g;
        #pragma unroll
        for (int m = 0; m < 2; m++) {
            const int cb = m * 8 + tg * 2;
            smf[r0 * 17 + cb]           = acc[t][m][0];
            smf[r0 * 17 + cb + 1]       = acc[t][m][1];
            smf[(r0 + 8) * 17 + cb]     = acc[t][m][2];
            smf[(r0 + 8) * 17 + cb + 1] = acc[t][m][3];
        }
    }
    __syncthreads();

    // ---- phase 2: exactly one row per thread ----
    {
        float hx[DM];
        #pragma unroll
        for (int j = 0; j < DM; j++) hx[j] = smf[tid * 17 + j];

        const long long grow  = row0 + tid;
        const long long hbase = (long long)batch * NC;
        const long long hblk  = (long long)batch * HID;

        #pragma unroll
        for (int ib = 0; ib < NB; ib++) {
            float h[HID];
            #pragma unroll
            for (int a = 0; a < HID; a++) {
                const float4* lp = (const float4*)(Lw + ib * (HID * DM) + a * DM);
                const float4* rp = (const float4*)(Rw + ib * (HID * DM) + a * DM);
                float su = 0.f, sv = 0.f;
                #pragma unroll
                for (int q = 0; q < 4; q++) {
                    float4 l4 = __ldg(lp + q), r4 = __ldg(rp + q);
                    su = fmaf(l4.x, hx[q*4+0], fmaf(l4.y, hx[q*4+1],
                         fmaf(l4.z, hx[q*4+2], fmaf(l4.w, hx[q*4+3], su))));
                    sv = fmaf(r4.x, hx[q*4+0], fmaf(r4.y, hx[q*4+1],
                         fmaf(r4.z, hx[q*4+2], fmaf(r4.w, hx[q*4+3], sv))));
                }
                h[a] = su * sv;
            }
            {
                float* hp = out + hbase + (long long)ib * hblk + grow * HID;
                *(float2*)(hp + 0) = make_float2(h[0], h[1]);
                *(float2*)(hp + 2) = make_float2(h[2], h[3]);
                *(float2*)(hp + 4) = make_float2(h[4], h[5]);
            }
            #pragma unroll
            for (int a = 0; a < HID; a++) {
                const float4* dp = (const float4*)(g_Dt + ib * (DM * HID) + a * DM);
                #pragma unroll
                for (int q = 0; q < 4; q++) {
                    float4 d4 = dp[q];
                    hx[q*4+0] = fmaf(h[a], d4.x, hx[q*4+0]);
                    hx[q*4+1] = fmaf(h[a], d4.y, hx[q*4+1]);
                    hx[q*4+2] = fmaf(h[a], d4.z, hx[q*4+2]);
                    hx[q*4+3] = fmaf(h[a], d4.w, hx[q*4+3]);
                }
            }
        }

        float lg[NC];
        #pragma unroll
        for (int cc = 0; cc < NC; cc++) {
            const float4* wp = (const float4*)(Wh + cc * DM);
            float s = 0.f;
            #pragma unroll
            for (int q = 0; q < 4; q++) {
                float4 w4 = __ldg(wp + q);
                s = fmaf(w4.x, hx[q*4+0], fmaf(w4.y, hx[q*4+1],
                    fmaf(w4.z, hx[q*4+2], fmaf(w4.w, hx[q*4+3], s))));
            }
            lg[cc] = s;
        }
        float* op = out + grow * NC;
        *(float2*)(op + 0) = make_float2(lg[0], lg[1]);
        *(float2*)(op + 2) = make_float2(lg[2], lg[3]);
        *(float2*)(op + 4) = make_float2(lg[4], lg[5]);
        *(float2*)(op + 6) = make_float2(lg[6], lg[7]);
        *(float2*)(op + 8) = make_float2(lg[8], lg[9]);
    }
}

typedef CUresult (*PFN_encodeTiled)(
    CUtensorMap*, CUtensorMapDataType, cuuint32_t, void*,
    const cuuint64_t*, const cuuint64_t*, const cuuint32_t*, const cuuint32_t*,
    CUtensorMapInterleave, CUtensorMapSwizzle, CUtensorMapL2promotion,
    CUtensorMapFloatOOBfill);

extern "C" void kernel_launch(void* const* d_in, const int* in_sizes, int n_in,
                              void* d_out, int out_size)
{
    const float* x  = (const float*)d_in[0];
    const float* We = (const float*)d_in[1];
    const float* Lw = (const float*)d_in[2];
    const float* Rw = (const float*)d_in[3];
    const float* Dw = (const float*)d_in[4];
    const float* Wh = (const float*)d_in[5];
    float* out = (float*)d_out;

    int batch = in_sizes[0] / IN_DIM;   // 65536
    int grid  = batch / TROWS;          // 1024

    // x tensor map: [784, batch] fp32, box [32, 64], SW128, OOB -> zero
    CUtensorMap tmap;
    {
        void* fp = nullptr;
        cudaDriverEntryPointQueryResult st;
        cudaGetDriverEntryPoint("cuTensorMapEncodeTiled", &fp,
                                cudaEnableDefault, &st);
        PFN_encodeTiled enc = (PFN_encodeTiled)fp;
        cuuint64_t dims[2]    = {IN_DIM, (cuuint64_t)batch};
        cuuint64_t strides[1] = {IN_DIM * sizeof(float)};
        cuuint32_t box[2]     = {KC, TROWS};
        cuuint32_t estr[2]    = {1, 1};
        enc(&tmap, CU_TENSOR_MAP_DATA_TYPE_FLOAT32, 2, (void*)x,
            dims, strides, box, estr,
            CU_TENSOR_MAP_INTERLEAVE_NONE, CU_TENSOR_MAP_SWIZZLE_128B,
            CU_TENSOR_MAP_L2_PROMOTION_L2_128B, CU_TENSOR_MAP_FLOAT_OOB_FILL_NONE);
    }

    reorder_kernel<<<(NW + 255) / 256, 256>>>(We, Dw);

    cudaFuncSetAttribute(bilinear_resnet_kernel,
                         cudaFuncAttributeMaxDynamicSharedMemorySize, SMEM_BYTES);
    bilinear_resnet_kernel<<<grid, NTH, SMEM_BYTES>>>(tmap, Lw, Rw, Wh, out, batch);
}